// round 1
// baseline (speedup 1.0000x reference)
#include <cuda_runtime.h>
#include <math.h>

// Problem constants
#define B_ 16
#define S_ 2048
#define D_ 128
#define SCALE_ 0.08838834764831845f  // 1/sqrt(128)

// ---------------------------------------------------------------------------
// Kernel 1: scores[b,q,k] = (Q[b,q,:] . K[b,k,:]) * SCALE + mask[q,k]
// Tiled GEMM: BM=64, BN=64, BK=32. 256 threads, each computes 4x4.
// Smem tiles stored transposed [k][row] so inner loads are float4 & conflict-free.
// ---------------------------------------------------------------------------
__global__ __launch_bounds__(256) void scores_kernel(
    const float* __restrict__ q,
    const float* __restrict__ k,
    const float* __restrict__ mask,
    float* __restrict__ attn)
{
    __shared__ float QsT[32][68];  // [k_local][row], stride 68 floats (16B aligned)
    __shared__ float KsT[32][68];

    const int b  = blockIdx.z;
    const int qt = blockIdx.y * 64;
    const int kt = blockIdx.x * 64;

    const float* qb = q + (size_t)b * S_ * D_;
    const float* kb = k + (size_t)b * S_ * D_;

    const int tid = threadIdx.x;       // 0..255
    const int tx  = tid % 16;          // col group
    const int ty  = tid / 16;          // row group

    float acc[4][4];
#pragma unroll
    for (int i = 0; i < 4; i++)
#pragma unroll
        for (int j = 0; j < 4; j++) acc[i][j] = 0.0f;

    for (int d0 = 0; d0 < D_; d0 += 32) {
        // Load 64x32 Q tile and 64x32 K tile (transposed into smem).
        // 64*32 = 2048 floats = 512 float4; 256 threads -> 2 float4 each.
#pragma unroll
        for (int t = 0; t < 2; t++) {
            int idx = tid + t * 256;       // float4 index in tile
            int row = idx >> 3;            // 8 float4 per row
            int c4  = (idx & 7) * 4;       // starting col within 32
            float4 vq = *(const float4*)&qb[(size_t)(qt + row) * D_ + d0 + c4];
            float4 vk = *(const float4*)&kb[(size_t)(kt + row) * D_ + d0 + c4];
            QsT[c4 + 0][row] = vq.x; QsT[c4 + 1][row] = vq.y;
            QsT[c4 + 2][row] = vq.z; QsT[c4 + 3][row] = vq.w;
            KsT[c4 + 0][row] = vk.x; KsT[c4 + 1][row] = vk.y;
            KsT[c4 + 2][row] = vk.z; KsT[c4 + 3][row] = vk.w;
        }
        __syncthreads();

#pragma unroll
        for (int kk = 0; kk < 32; kk++) {
            float4 a4 = *(const float4*)&QsT[kk][ty * 4];
            float4 b4 = *(const float4*)&KsT[kk][tx * 4];
            float a[4] = {a4.x, a4.y, a4.z, a4.w};
            float bb[4] = {b4.x, b4.y, b4.z, b4.w};
#pragma unroll
            for (int i = 0; i < 4; i++)
#pragma unroll
                for (int j = 0; j < 4; j++)
                    acc[i][j] = fmaf(a[i], bb[j], acc[i][j]);
        }
        __syncthreads();
    }

    // Epilogue: scale, add mask, write float4 rows.
#pragma unroll
    for (int i = 0; i < 4; i++) {
        int qrow = qt + ty * 4 + i;
        int kcol = kt + tx * 4;
        float4 m4 = *(const float4*)&mask[(size_t)qrow * S_ + kcol];
        float4 o;
        o.x = acc[i][0] * SCALE_ + m4.x;
        o.y = acc[i][1] * SCALE_ + m4.y;
        o.z = acc[i][2] * SCALE_ + m4.z;
        o.w = acc[i][3] * SCALE_ + m4.w;
        *(float4*)&attn[((size_t)b * S_ + qrow) * S_ + kcol] = o;
    }
}

// ---------------------------------------------------------------------------
// Kernel 2: in-place row softmax over attn. One 256-thread CTA per row (2048).
// Each thread holds 8 values (2 float4) in registers.
// ---------------------------------------------------------------------------
__global__ __launch_bounds__(256) void softmax_kernel(float* __restrict__ attn)
{
    __shared__ float red[256];
    const size_t row = blockIdx.x;
    float* p = attn + row * (size_t)S_;
    const int tid = threadIdx.x;

    float4 v0 = ((const float4*)p)[tid];
    float4 v1 = ((const float4*)p)[tid + 256];

    float m = fmaxf(fmaxf(fmaxf(v0.x, v0.y), fmaxf(v0.z, v0.w)),
                    fmaxf(fmaxf(v1.x, v1.y), fmaxf(v1.z, v1.w)));
    red[tid] = m;
    __syncthreads();
#pragma unroll
    for (int s = 128; s > 0; s >>= 1) {
        if (tid < s) red[tid] = fmaxf(red[tid], red[tid + s]);
        __syncthreads();
    }
    m = red[0];
    __syncthreads();

    v0.x = expf(v0.x - m); v0.y = expf(v0.y - m);
    v0.z = expf(v0.z - m); v0.w = expf(v0.w - m);
    v1.x = expf(v1.x - m); v1.y = expf(v1.y - m);
    v1.z = expf(v1.z - m); v1.w = expf(v1.w - m);

    float sum = (v0.x + v0.y) + (v0.z + v0.w) + (v1.x + v1.y) + (v1.z + v1.w);
    red[tid] = sum;
    __syncthreads();
#pragma unroll
    for (int s = 128; s > 0; s >>= 1) {
        if (tid < s) red[tid] += red[tid + s];
        __syncthreads();
    }
    float inv = 1.0f / red[0];

    v0.x *= inv; v0.y *= inv; v0.z *= inv; v0.w *= inv;
    v1.x *= inv; v1.y *= inv; v1.z *= inv; v1.w *= inv;
    ((float4*)p)[tid]       = v0;
    ((float4*)p)[tid + 256] = v1;
}

// ---------------------------------------------------------------------------
// Kernel 3: out[b,q,d] = sum_k attn[b,q,k] * V[b,k,d]
// Tiled GEMM: BM=32 (q rows), BN=128 (all of D), BK=32.
// 256 threads = 32(tx) x 8(ty), each computes 4 rows x 4 cols.
// ---------------------------------------------------------------------------
__global__ __launch_bounds__(256) void out_kernel(
    const float* __restrict__ attn,
    const float* __restrict__ v,
    float* __restrict__ out)
{
    __shared__ float PsT[32][36];   // [k_local][q_row], stride 36 (16B aligned)
    __shared__ float Vs[32][132];   // [k_local][d],     stride 132 (16B aligned)

    const int b  = blockIdx.y;
    const int qt = blockIdx.x * 32;

    const float* pb = attn + ((size_t)b * S_ + qt) * S_;
    const float* vb = v + (size_t)b * S_ * D_;

    const int tid = threadIdx.x;  // 0..255
    const int tx  = tid % 32;     // col group (d)
    const int ty  = tid / 32;     // row group (q)

    float acc[4][4];
#pragma unroll
    for (int i = 0; i < 4; i++)
#pragma unroll
        for (int j = 0; j < 4; j++) acc[i][j] = 0.0f;

    for (int k0 = 0; k0 < S_; k0 += 32) {
        // Load P tile 32x32 (transposed): 1024 floats = 256 float4, 1 per thread.
        {
            int idx = tid;
            int row = idx >> 3;           // q row within tile
            int c4  = (idx & 7) * 4;      // k col within tile
            float4 vp = *(const float4*)&pb[(size_t)row * S_ + k0 + c4];
            PsT[c4 + 0][row] = vp.x; PsT[c4 + 1][row] = vp.y;
            PsT[c4 + 2][row] = vp.z; PsT[c4 + 3][row] = vp.w;
        }
        // Load V tile 32x128: 4096 floats = 1024 float4, 4 per thread.
#pragma unroll
        for (int t = 0; t < 4; t++) {
            int idx = tid + t * 256;
            int row = idx >> 5;           // k row within tile
            int c4  = (idx & 31) * 4;     // d col
            float4 vv = *(const float4*)&vb[(size_t)(k0 + row) * D_ + c4];
            *(float4*)&Vs[row][c4] = vv;
        }
        __syncthreads();

#pragma unroll
        for (int kk = 0; kk < 32; kk++) {
            float4 a4 = *(const float4*)&PsT[kk][ty * 4];
            float4 b4 = *(const float4*)&Vs[kk][tx * 4];
            float a[4] = {a4.x, a4.y, a4.z, a4.w};
            float bb[4] = {b4.x, b4.y, b4.z, b4.w};
#pragma unroll
            for (int i = 0; i < 4; i++)
#pragma unroll
                for (int j = 0; j < 4; j++)
                    acc[i][j] = fmaf(a[i], bb[j], acc[i][j]);
        }
        __syncthreads();
    }

#pragma unroll
    for (int i = 0; i < 4; i++) {
        int qrow = qt + ty * 4 + i;
        int dcol = tx * 4;
        float4 o = {acc[i][0], acc[i][1], acc[i][2], acc[i][3]};
        *(float4*)&out[((size_t)b * S_ + qrow) * D_ + dcol] = o;
    }
}

// ---------------------------------------------------------------------------
// Launch: d_out = [output (B*S*D) | attn (B*S*S)]  (tuple order of reference)
// ---------------------------------------------------------------------------
extern "C" void kernel_launch(void* const* d_in, const int* in_sizes, int n_in,
                              void* d_out, int out_size)
{
    const float* q    = (const float*)d_in[0];
    const float* k    = (const float*)d_in[1];
    const float* v    = (const float*)d_in[2];
    const float* mask = (const float*)d_in[3];

    float* out  = (float*)d_out;
    float* attn = out + (size_t)B_ * S_ * D_;

    dim3 g1(S_ / 64, S_ / 64, B_);          // 32 x 32 x 16
    scores_kernel<<<g1, 256>>>(q, k, mask, attn);

    softmax_kernel<<<B_ * S_, 256>>>(attn); // 32768 rows

    dim3 g3(S_ / 32, B_);                   // 64 x 16
    out_kernel<<<g3, 256>>>(attn, v, out);
}

// round 2
// speedup vs baseline: 1.2391x; 1.2391x over previous
#include <cuda_runtime.h>
#include <math.h>

#define B_ 16
#define S_ 2048
#define D_ 128
#define SCALE_ 0.08838834764831845f  // 1/sqrt(128)

// Padded smem stride: 132 words -> conflict-free transposed stores & quadrant loads.
#define LDA_ 132

// ---------------------------------------------------------------------------
// Kernel 1: scores[b,q,k] = (Q[b,q,:].K[b,k,:]) * SCALE + mask[q,k]
// 128x128 CTA tile, BK=16, 256 threads, 8x8 per thread (2x2 float4 quadrants).
// ---------------------------------------------------------------------------
__global__ __launch_bounds__(256, 2) void scores_kernel(
    const float* __restrict__ q,
    const float* __restrict__ k,
    const float* __restrict__ mask,
    float* __restrict__ attn)
{
    __shared__ float Qs[16][LDA_];  // [d][q-row]
    __shared__ float Ks[16][LDA_];  // [d][k-col]

    const int b  = blockIdx.z;
    const int qt = blockIdx.y * 128;
    const int kt = blockIdx.x * 128;

    const float* qb = q + (size_t)b * S_ * D_;
    const float* kb = k + (size_t)b * S_ * D_;

    const int tid = threadIdx.x;   // 0..255
    const int tx  = tid & 15;      // col group
    const int ty  = tid >> 4;      // row group

    // Precompute load coords (128 rows x 16 cols = 512 float4; 2 per thread)
    const int l_row0 = (tid)        >> 2;
    const int l_c40  = ((tid)  & 3) * 4;
    const int l_row1 = (tid + 256)  >> 2;
    const int l_c41  = ((tid + 256) & 3) * 4;

    float acc[8][8];
#pragma unroll
    for (int i = 0; i < 8; i++)
#pragma unroll
        for (int j = 0; j < 8; j++) acc[i][j] = 0.0f;

#pragma unroll 1
    for (int d0 = 0; d0 < D_; d0 += 16) {
        float4 vq0 = *(const float4*)&qb[(size_t)(qt + l_row0) * D_ + d0 + l_c40];
        float4 vq1 = *(const float4*)&qb[(size_t)(qt + l_row1) * D_ + d0 + l_c41];
        float4 vk0 = *(const float4*)&kb[(size_t)(kt + l_row0) * D_ + d0 + l_c40];
        float4 vk1 = *(const float4*)&kb[(size_t)(kt + l_row1) * D_ + d0 + l_c41];

        Qs[l_c40 + 0][l_row0] = vq0.x; Qs[l_c40 + 1][l_row0] = vq0.y;
        Qs[l_c40 + 2][l_row0] = vq0.z; Qs[l_c40 + 3][l_row0] = vq0.w;
        Qs[l_c41 + 0][l_row1] = vq1.x; Qs[l_c41 + 1][l_row1] = vq1.y;
        Qs[l_c41 + 2][l_row1] = vq1.z; Qs[l_c41 + 3][l_row1] = vq1.w;
        Ks[l_c40 + 0][l_row0] = vk0.x; Ks[l_c40 + 1][l_row0] = vk0.y;
        Ks[l_c40 + 2][l_row0] = vk0.z; Ks[l_c40 + 3][l_row0] = vk0.w;
        Ks[l_c41 + 0][l_row1] = vk1.x; Ks[l_c41 + 1][l_row1] = vk1.y;
        Ks[l_c41 + 2][l_row1] = vk1.z; Ks[l_c41 + 3][l_row1] = vk1.w;
        __syncthreads();

#pragma unroll
        for (int kk = 0; kk < 16; kk++) {
            float4 a0 = *(const float4*)&Qs[kk][ty * 4];
            float4 a1 = *(const float4*)&Qs[kk][ty * 4 + 64];
            float4 b0 = *(const float4*)&Ks[kk][tx * 4];
            float4 b1 = *(const float4*)&Ks[kk][tx * 4 + 64];
            float a[8] = {a0.x, a0.y, a0.z, a0.w, a1.x, a1.y, a1.z, a1.w};
            float bb[8] = {b0.x, b0.y, b0.z, b0.w, b1.x, b1.y, b1.z, b1.w};
#pragma unroll
            for (int i = 0; i < 8; i++)
#pragma unroll
                for (int j = 0; j < 8; j++)
                    acc[i][j] = fmaf(a[i], bb[j], acc[i][j]);
        }
        __syncthreads();
    }

    // Epilogue: scale + mask, 16 float4 stores.
#pragma unroll
    for (int i = 0; i < 8; i++) {
        int qrow = qt + ty * 4 + (i < 4 ? i : 64 + i - 4);
        size_t rowbase = ((size_t)b * S_ + qrow) * S_;
        size_t mbase   = (size_t)qrow * S_;
#pragma unroll
        for (int jq = 0; jq < 2; jq++) {
            int kcol = kt + tx * 4 + jq * 64;
            float4 m4 = *(const float4*)&mask[mbase + kcol];
            float4 o;
            o.x = acc[i][jq * 4 + 0] * SCALE_ + m4.x;
            o.y = acc[i][jq * 4 + 1] * SCALE_ + m4.y;
            o.z = acc[i][jq * 4 + 2] * SCALE_ + m4.z;
            o.w = acc[i][jq * 4 + 3] * SCALE_ + m4.w;
            *(float4*)&attn[rowbase + kcol] = o;
        }
    }
}

// ---------------------------------------------------------------------------
// Kernel 2: in-place row softmax. One 256-thread CTA per row.
// ---------------------------------------------------------------------------
__global__ __launch_bounds__(256) void softmax_kernel(float* __restrict__ attn)
{
    __shared__ float red[256];
    const size_t row = blockIdx.x;
    float* p = attn + row * (size_t)S_;
    const int tid = threadIdx.x;

    float4 v0 = ((const float4*)p)[tid];
    float4 v1 = ((const float4*)p)[tid + 256];

    float m = fmaxf(fmaxf(fmaxf(v0.x, v0.y), fmaxf(v0.z, v0.w)),
                    fmaxf(fmaxf(v1.x, v1.y), fmaxf(v1.z, v1.w)));
    red[tid] = m;
    __syncthreads();
#pragma unroll
    for (int s = 128; s > 0; s >>= 1) {
        if (tid < s) red[tid] = fmaxf(red[tid], red[tid + s]);
        __syncthreads();
    }
    m = red[0];
    __syncthreads();

    v0.x = __expf(v0.x - m); v0.y = __expf(v0.y - m);
    v0.z = __expf(v0.z - m); v0.w = __expf(v0.w - m);
    v1.x = __expf(v1.x - m); v1.y = __expf(v1.y - m);
    v1.z = __expf(v1.z - m); v1.w = __expf(v1.w - m);

    float sum = (v0.x + v0.y) + (v0.z + v0.w) + (v1.x + v1.y) + (v1.z + v1.w);
    red[tid] = sum;
    __syncthreads();
#pragma unroll
    for (int s = 128; s > 0; s >>= 1) {
        if (tid < s) red[tid] += red[tid + s];
        __syncthreads();
    }
    float inv = 1.0f / red[0];

    v0.x *= inv; v0.y *= inv; v0.z *= inv; v0.w *= inv;
    v1.x *= inv; v1.y *= inv; v1.z *= inv; v1.w *= inv;
    ((float4*)p)[tid]       = v0;
    ((float4*)p)[tid + 256] = v1;
}

// ---------------------------------------------------------------------------
// Kernel 3: out[b,q,d] = sum_k attn[b,q,k] * V[b,k,d]
// BM=128 (q), BN=128 (=D), BK=16, 256 threads, 8x8 per thread.
// ---------------------------------------------------------------------------
__global__ __launch_bounds__(256, 2) void out_kernel(
    const float* __restrict__ attn,
    const float* __restrict__ v,
    float* __restrict__ out)
{
    __shared__ float Ps[16][LDA_];  // [k][q-row] (transposed)
    __shared__ float Vs[16][LDA_];  // [k][d]

    const int b  = blockIdx.y;
    const int qt = blockIdx.x * 128;

    const float* pb = attn + ((size_t)b * S_ + qt) * S_;
    const float* vb = v + (size_t)b * S_ * D_;

    const int tid = threadIdx.x;
    const int tx  = tid & 15;
    const int ty  = tid >> 4;

    // P load coords: 128 rows x 16 k = 512 float4, 2 per thread (transpose)
    const int p_row0 = (tid)        >> 2;
    const int p_c40  = ((tid)  & 3) * 4;
    const int p_row1 = (tid + 256)  >> 2;
    const int p_c41  = ((tid + 256) & 3) * 4;
    // V load coords: 16 rows x 128 d = 512 float4, 2 per thread (direct)
    const int v_row0 = (tid)        >> 5;
    const int v_c40  = ((tid)  & 31) * 4;
    const int v_row1 = (tid + 256)  >> 5;
    const int v_c41  = ((tid + 256) & 31) * 4;

    float acc[8][8];
#pragma unroll
    for (int i = 0; i < 8; i++)
#pragma unroll
        for (int j = 0; j < 8; j++) acc[i][j] = 0.0f;

#pragma unroll 1
    for (int k0 = 0; k0 < S_; k0 += 16) {
        float4 vp0 = *(const float4*)&pb[(size_t)p_row0 * S_ + k0 + p_c40];
        float4 vp1 = *(const float4*)&pb[(size_t)p_row1 * S_ + k0 + p_c41];
        float4 vv0 = *(const float4*)&vb[(size_t)(k0 + v_row0) * D_ + v_c40];
        float4 vv1 = *(const float4*)&vb[(size_t)(k0 + v_row1) * D_ + v_c41];

        Ps[p_c40 + 0][p_row0] = vp0.x; Ps[p_c40 + 1][p_row0] = vp0.y;
        Ps[p_c40 + 2][p_row0] = vp0.z; Ps[p_c40 + 3][p_row0] = vp0.w;
        Ps[p_c41 + 0][p_row1] = vp1.x; Ps[p_c41 + 1][p_row1] = vp1.y;
        Ps[p_c41 + 2][p_row1] = vp1.z; Ps[p_c41 + 3][p_row1] = vp1.w;
        *(float4*)&Vs[v_row0][v_c40] = vv0;
        *(float4*)&Vs[v_row1][v_c41] = vv1;
        __syncthreads();

#pragma unroll
        for (int kk = 0; kk < 16; kk++) {
            float4 a0 = *(const float4*)&Ps[kk][ty * 4];
            float4 a1 = *(const float4*)&Ps[kk][ty * 4 + 64];
            float4 b0 = *(const float4*)&Vs[kk][tx * 4];
            float4 b1 = *(const float4*)&Vs[kk][tx * 4 + 64];
            float a[8] = {a0.x, a0.y, a0.z, a0.w, a1.x, a1.y, a1.z, a1.w};
            float bb[8] = {b0.x, b0.y, b0.z, b0.w, b1.x, b1.y, b1.z, b1.w};
#pragma unroll
            for (int i = 0; i < 8; i++)
#pragma unroll
                for (int j = 0; j < 8; j++)
                    acc[i][j] = fmaf(a[i], bb[j], acc[i][j]);
        }
        __syncthreads();
    }

#pragma unroll
    for (int i = 0; i < 8; i++) {
        int qrow = qt + ty * 4 + (i < 4 ? i : 64 + i - 4);
        size_t rowbase = ((size_t)b * S_ + qrow) * D_;
#pragma unroll
        for (int jq = 0; jq < 2; jq++) {
            int dcol = tx * 4 + jq * 64;
            float4 o = {acc[i][jq * 4 + 0], acc[i][jq * 4 + 1],
                        acc[i][jq * 4 + 2], acc[i][jq * 4 + 3]};
            *(float4*)&out[rowbase + dcol] = o;
        }
    }
}

// ---------------------------------------------------------------------------
// d_out = [output (B*S*D) | attn (B*S*S)]
// ---------------------------------------------------------------------------
extern "C" void kernel_launch(void* const* d_in, const int* in_sizes, int n_in,
                              void* d_out, int out_size)
{
    const float* q    = (const float*)d_in[0];
    const float* k    = (const float*)d_in[1];
    const float* v    = (const float*)d_in[2];
    const float* mask = (const float*)d_in[3];

    float* out  = (float*)d_out;
    float* attn = out + (size_t)B_ * S_ * D_;

    dim3 g1(S_ / 128, S_ / 128, B_);   // 16 x 16 x 16
    scores_kernel<<<g1, 256>>>(q, k, mask, attn);

    softmax_kernel<<<B_ * S_, 256>>>(attn);

    dim3 g3(S_ / 128, B_);             // 16 x 16
    out_kernel<<<g3, 256>>>(attn, v, out);
}

// round 4
// speedup vs baseline: 2.5728x; 2.0763x over previous
#include <cuda_runtime.h>
#include <cstdint>

#define B_ 16
#define S_ 2048
#define D_ 128
#define SCALE_ 0.08838834764831845f  // 1/sqrt(128)

#define LDK_ 36    // 32-wide k tiles + 4 pad  -> bank = 4*row + col (conflict-free frags)
#define LDN_ 136   // 128-wide n tiles + 8 pad -> bank = 8*row + col (conflict-free frags)

// tf32 round (rna)
__device__ __forceinline__ uint32_t tf32r(float f) {
    uint32_t r;
    asm("cvt.rna.tf32.f32 %0, %1;" : "=r"(r) : "f"(f));
    return r;
}

// D += A*B, m16n8k8 tf32
__device__ __forceinline__ void mma8(float* d, uint32_t a0, uint32_t a1, uint32_t a2,
                                     uint32_t a3, uint32_t b0, uint32_t b1) {
    asm volatile(
        "mma.sync.aligned.m16n8k8.row.col.f32.tf32.tf32.f32 "
        "{%0,%1,%2,%3}, {%4,%5,%6,%7}, {%8,%9}, {%0,%1,%2,%3};"
        : "+f"(d[0]), "+f"(d[1]), "+f"(d[2]), "+f"(d[3])
        : "r"(a0), "r"(a1), "r"(a2), "r"(a3), "r"(b0), "r"(b1));
}

// =====================================================================
// Kernel 1: scores[b,q,k] = (Q.K^T)*SCALE + mask
// CTA 128x128, BK=32. 8 warps = 2(m) x 4(n); warp tile 64x32.
// =====================================================================
__global__ __launch_bounds__(256, 2) void scores_mma(
    const float* __restrict__ q, const float* __restrict__ k,
    const float* __restrict__ mask, float* __restrict__ attn)
{
    __shared__ float Qs[128][LDK_];   // [m][k]
    __shared__ float Ks[128][LDK_];   // [n][k]

    const int b  = blockIdx.x;
    const int kt = blockIdx.y * 128;
    const int qt = blockIdx.z * 128;

    const float* qb = q + ((size_t)b * S_ + qt) * D_;
    const float* kb = k + ((size_t)b * S_ + kt) * D_;

    const int tid  = threadIdx.x;
    const int wid  = tid >> 5, lane = tid & 31;
    const int g    = lane >> 2, c = lane & 3;
    const int wm   = (wid & 1) * 64;    // warp m offset
    const int wn   = (wid >> 1) * 32;   // warp n offset

    float acc[4][4][4];
#pragma unroll
    for (int mi = 0; mi < 4; mi++)
#pragma unroll
        for (int ni = 0; ni < 4; ni++)
#pragma unroll
            for (int r = 0; r < 4; r++) acc[mi][ni][r] = 0.0f;

#pragma unroll 1
    for (int d0 = 0; d0 < D_; d0 += 32) {
        // Load 128x32 chunks of Q and K (tf32-rounded), row-major stride LDK_.
#pragma unroll
        for (int t = 0; t < 4; t++) {
            const int idx = tid + t * 256;
            const int row = idx >> 3, c4 = (idx & 7) * 4;
            const float4 vq = *(const float4*)&qb[(size_t)row * D_ + d0 + c4];
            const float4 vk = *(const float4*)&kb[(size_t)row * D_ + d0 + c4];
            uint4 uq = { tf32r(vq.x), tf32r(vq.y), tf32r(vq.z), tf32r(vq.w) };
            uint4 uk = { tf32r(vk.x), tf32r(vk.y), tf32r(vk.z), tf32r(vk.w) };
            *(uint4*)&Qs[row][c4] = uq;
            *(uint4*)&Ks[row][c4] = uk;
        }
        __syncthreads();

#pragma unroll
        for (int kk = 0; kk < 4; kk++) {
            const int co = kk * 8;
            uint32_t bf[4][2];
#pragma unroll
            for (int ni = 0; ni < 4; ni++) {
                const int col = wn + ni * 8 + g;
                bf[ni][0] = __float_as_uint(Ks[col][co + c]);
                bf[ni][1] = __float_as_uint(Ks[col][co + c + 4]);
            }
#pragma unroll
            for (int mi = 0; mi < 4; mi++) {
                const int row = wm + mi * 16 + g;
                const uint32_t a0 = __float_as_uint(Qs[row][co + c]);
                const uint32_t a1 = __float_as_uint(Qs[row + 8][co + c]);
                const uint32_t a2 = __float_as_uint(Qs[row][co + c + 4]);
                const uint32_t a3 = __float_as_uint(Qs[row + 8][co + c + 4]);
#pragma unroll
                for (int ni = 0; ni < 4; ni++)
                    mma8(acc[mi][ni], a0, a1, a2, a3, bf[ni][0], bf[ni][1]);
            }
        }
        __syncthreads();
    }

    // Epilogue: scale + mask, float2 stores.
#pragma unroll
    for (int mi = 0; mi < 4; mi++) {
#pragma unroll
        for (int rr = 0; rr < 2; rr++) {
            const int qrow = qt + wm + mi * 16 + g + rr * 8;
            const float* mrow = mask + (size_t)qrow * S_ + kt;
            float* arow = attn + ((size_t)b * S_ + qrow) * S_ + kt;
#pragma unroll
            for (int ni = 0; ni < 4; ni++) {
                const int col = wn + ni * 8 + c * 2;
                const float2 m2 = *(const float2*)&mrow[col];
                float2 o;
                o.x = acc[mi][ni][rr * 2 + 0] * SCALE_ + m2.x;
                o.y = acc[mi][ni][rr * 2 + 1] * SCALE_ + m2.y;
                *(float2*)&arow[col] = o;
            }
        }
    }
}

// =====================================================================
// Kernel 2: in-place row softmax. One 256-thread CTA per row.
// =====================================================================
__global__ __launch_bounds__(256) void softmax_kernel(float* __restrict__ attn)
{
    __shared__ float red[256];
    const size_t row = blockIdx.x;
    float* p = attn + row * (size_t)S_;
    const int tid = threadIdx.x;

    float4 v0 = ((const float4*)p)[tid];
    float4 v1 = ((const float4*)p)[tid + 256];

    float m = fmaxf(fmaxf(fmaxf(v0.x, v0.y), fmaxf(v0.z, v0.w)),
                    fmaxf(fmaxf(v1.x, v1.y), fmaxf(v1.z, v1.w)));
    red[tid] = m;
    __syncthreads();
#pragma unroll
    for (int s = 128; s > 0; s >>= 1) {
        if (tid < s) red[tid] = fmaxf(red[tid], red[tid + s]);
        __syncthreads();
    }
    m = red[0];
    __syncthreads();

    v0.x = __expf(v0.x - m); v0.y = __expf(v0.y - m);
    v0.z = __expf(v0.z - m); v0.w = __expf(v0.w - m);
    v1.x = __expf(v1.x - m); v1.y = __expf(v1.y - m);
    v1.z = __expf(v1.z - m); v1.w = __expf(v1.w - m);

    float sum = (v0.x + v0.y) + (v0.z + v0.w) + (v1.x + v1.y) + (v1.z + v1.w);
    red[tid] = sum;
    __syncthreads();
#pragma unroll
    for (int s = 128; s > 0; s >>= 1) {
        if (tid < s) red[tid] += red[tid + s];
        __syncthreads();
    }
    const float inv = 1.0f / red[0];

    v0.x *= inv; v0.y *= inv; v0.z *= inv; v0.w *= inv;
    v1.x *= inv; v1.y *= inv; v1.z *= inv; v1.w *= inv;
    ((float4*)p)[tid]       = v0;
    ((float4*)p)[tid + 256] = v1;
}

// =====================================================================
// Kernel 3: out[b,q,d] = sum_s P[b,q,s] * V[b,s,d]
// CTA 128(q) x 128(d), K=2048 in BK=32 chunks. V natural layout = [k][n].
// =====================================================================
__global__ __launch_bounds__(256, 2) void out_mma(
    const float* __restrict__ attn, const float* __restrict__ v,
    float* __restrict__ out)
{
    __shared__ float Ps[128][LDK_];   // [m][k]
    __shared__ float Vs[32][LDN_];    // [k][n]

    const int b  = blockIdx.x;
    const int qt = blockIdx.y * 128;

    const float* pb = attn + ((size_t)b * S_ + qt) * S_;
    const float* vb = v + (size_t)b * S_ * D_;

    const int tid  = threadIdx.x;
    const int wid  = tid >> 5, lane = tid & 31;
    const int g    = lane >> 2, c = lane & 3;
    const int wm   = (wid & 1) * 64;
    const int wn   = (wid >> 1) * 32;

    float acc[4][4][4];
#pragma unroll
    for (int mi = 0; mi < 4; mi++)
#pragma unroll
        for (int ni = 0; ni < 4; ni++)
#pragma unroll
            for (int r = 0; r < 4; r++) acc[mi][ni][r] = 0.0f;

#pragma unroll 1
    for (int k0 = 0; k0 < S_; k0 += 32) {
        // P chunk: 128 rows x 32 k
#pragma unroll
        for (int t = 0; t < 4; t++) {
            const int idx = tid + t * 256;
            const int row = idx >> 3, c4 = (idx & 7) * 4;
            const float4 vp = *(const float4*)&pb[(size_t)row * S_ + k0 + c4];
            uint4 up = { tf32r(vp.x), tf32r(vp.y), tf32r(vp.z), tf32r(vp.w) };
            *(uint4*)&Ps[row][c4] = up;
        }
        // V chunk: 32 k-rows x 128 d
#pragma unroll
        for (int t = 0; t < 4; t++) {
            const int idx = tid + t * 256;
            const int row = idx >> 5, c4 = (idx & 31) * 4;
            const float4 vv = *(const float4*)&vb[(size_t)(k0 + row) * D_ + c4];
            uint4 uv = { tf32r(vv.x), tf32r(vv.y), tf32r(vv.z), tf32r(vv.w) };
            *(uint4*)&Vs[row][c4] = uv;
        }
        __syncthreads();

#pragma unroll
        for (int kk = 0; kk < 4; kk++) {
            const int co = kk * 8;
            uint32_t bf[4][2];
#pragma unroll
            for (int ni = 0; ni < 4; ni++) {
                const int col = wn + ni * 8 + g;
                bf[ni][0] = __float_as_uint(Vs[co + c][col]);
                bf[ni][1] = __float_as_uint(Vs[co + c + 4][col]);
            }
#pragma unroll
            for (int mi = 0; mi < 4; mi++) {
                const int row = wm + mi * 16 + g;
                const uint32_t a0 = __float_as_uint(Ps[row][co + c]);
                const uint32_t a1 = __float_as_uint(Ps[row + 8][co + c]);
                const uint32_t a2 = __float_as_uint(Ps[row][co + c + 4]);
                const uint32_t a3 = __float_as_uint(Ps[row + 8][co + c + 4]);
#pragma unroll
                for (int ni = 0; ni < 4; ni++)
                    mma8(acc[mi][ni], a0, a1, a2, a3, bf[ni][0], bf[ni][1]);
            }
        }
        __syncthreads();
    }

#pragma unroll
    for (int mi = 0; mi < 4; mi++) {
#pragma unroll
        for (int rr = 0; rr < 2; rr++) {
            const int qrow = qt + wm + mi * 16 + g + rr * 8;
            float* orow = out + ((size_t)b * S_ + qrow) * D_;
#pragma unroll
            for (int ni = 0; ni < 4; ni++) {
                const int col = wn + ni * 8 + c * 2;
                float2 o = { acc[mi][ni][rr * 2 + 0], acc[mi][ni][rr * 2 + 1] };
                *(float2*)&orow[col] = o;
            }
        }
    }
}

// =====================================================================
// d_out = [output (B*S*D) | attn (B*S*S)]
// =====================================================================
extern "C" void kernel_launch(void* const* d_in, const int* in_sizes, int n_in,
                              void* d_out, int out_size)
{
    const float* q    = (const float*)d_in[0];
    const float* k    = (const float*)d_in[1];
    const float* v    = (const float*)d_in[2];
    const float* mask = (const float*)d_in[3];

    float* out  = (float*)d_out;
    float* attn = out + (size_t)B_ * S_ * D_;

    // b fastest -> mask/Q tiles shared in L2 across batch
    dim3 g1(B_, S_ / 128, S_ / 128);   // 16 x 16 x 16
    scores_mma<<<g1, 256>>>(q, k, mask, attn);

    softmax_kernel<<<B_ * S_, 256>>>(attn);

    dim3 g3(B_, S_ / 128);             // 16 x 16
    out_mma<<<g3, 256>>>(attn, v, out);
}